// round 15
// baseline (speedup 1.0000x reference)
#include <cuda_runtime.h>

#define IN_CH 16
#define OUT_CH 64
#define HDIM 32
#define WDIM 32
#define NB 8
#define KHW 9
#define F (IN_CH * KHW)      // 144
#define OCG 8                // out channels per block
#define ROWS 2               // output rows per block
#define NCP 16               // column pairs (2 cols/thread)
#define CSPLIT 4             // input-channel split
#define TPB 128              // 16 cp * 2 rows * 4 cs
#define TW 34                // tile width with halo
#define PSP 18               // ps inner stride
#define NPAIR 18             // tap pairs per channel-quarter

// packed fp32x2 add (Blackwell). pack/unpack movs are register-renaming noise
// that ptxas eliminates.
__device__ __forceinline__ float2 padd2f(float2 a, float2 b) {
    unsigned long long ua, ub, ur;
    asm("mov.b64 %0, {%1, %2};" : "=l"(ua) : "f"(a.x), "f"(a.y));
    asm("mov.b64 %0, {%1, %2};" : "=l"(ub) : "f"(b.x), "f"(b.y));
    asm("add.rn.f32x2 %0, %1, %2;" : "=l"(ur) : "l"(ua), "l"(ub));
    float2 r;
    asm("mov.b64 {%0, %1}, %2;" : "=f"(r.x), "=f"(r.y) : "l"(ur));
    return r;
}

__global__ __launch_bounds__(TPB, 8) void normdist_kernel(
    const float* __restrict__ x,      // (8,16,32,32)
    const float* __restrict__ weight, // (64,144)
    const float* __restrict__ bias,   // (64)
    float* __restrict__ out)          // (8,64,32,32)
{
    const int og  = blockIdx.x;            // 0..7 out-channel group
    const int rg  = blockIdx.y;            // 0..15 row group
    const int n   = blockIdx.z;            // 0..7 batch
    const int tid = threadIdx.x;
    const int cp  = tid & 15;              // 0..15 column pair
    const int r   = (tid >> 4) & 1;        // 0..1 row
    const int cs  = tid >> 5;              // 0..3 channel quarter (warp-uniform)

    const int row0 = rg * ROWS;

    __shared__ float xs[IN_CH][ROWS + 2][TW];                 // 8704 B
    // negated, pair-interleaved weights:
    // wP[cs][pf][o] = (-w[og*8+o][f0(pf)], -w[og*8+o][f1(pf)])
    __shared__ __align__(16) float2 wP[CSPLIT][NPAIR][OCG];   // 4608 B
    __shared__ float ps[CSPLIT - 1][ROWS][NCP][PSP];          // 6912 B

    // ---- weight loader: 576 float2 entries
    for (int idx = tid; idx < CSPLIT * NPAIR * OCG; idx += TPB) {
        int o    = idx & 7;
        int rest = idx >> 3;        // 0..71
        int pf   = rest % NPAIR;
        int csq  = rest / NPAIR;
        int f0, f1;
        if (pf < 12) {              // P pair: (ci,i) taps (j0,j1)
            int ci = pf / 3, i = pf % 3;
            f0 = (csq * 4 + ci) * KHW + i * 3;
            f1 = f0 + 1;
        } else {                    // R pair: (ch cp2*2, i, j2) with (ch cp2*2+1, i, j2)
            int t = pf - 12;
            int cp2 = t / 3, i = t % 3;
            f0 = (csq * 4 + cp2 * 2) * KHW + i * 3 + 2;
            f1 = f0 + KHW;
        }
        const float* wr = weight + (og * OCG + o) * F;
        wP[csq][pf][o] = make_float2(-wr[f0], -wr[f1]);
    }

    // ---- x tile with halo; shift-only indexing (64 (c,rr) pairs x 2 lanes)
    {
        const float* xn = x + (size_t)n * IN_CH * HDIM * WDIM;
        const int pair = tid >> 1;             // 0..63
        const int l2   = tid & 1;
        const int c    = pair >> 2;            // 0..15
        const int rr   = pair & 3;             // 0..3
        const int gr   = row0 - 1 + rr;
        const bool rok = (gr >= 0) && (gr < HDIM);
        const float* src = xn + (c * HDIM + gr) * WDIM;
        float* dst = &xs[c][rr][0];
        #pragma unroll
        for (int e = 0; e < 17; e++) {         // 17*2=34
            int cc = l2 + e * 2;
            int gc = cc - 1;
            float v = 0.0f;
            if (rok && gc >= 0 && gc < WDIM) v = src[gc];
            dst[cc] = v;
        }
    }
    __syncthreads();

    float accA[OCG], accB[OCG];
    #pragma unroll
    for (int o = 0; o < OCG; o++) { accA[o] = 0.0f; accB[o] = 0.0f; }

    // process one tap-pair pf for both columns
    auto do_pair = [&](int pf, float2 pA, float2 pB) {
        const float4* wq = reinterpret_cast<const float4*>(&wP[cs][pf][0]);
        #pragma unroll
        for (int h = 0; h < 4; h++) {          // 4x LDS.128, 2 ocs each
            float4 w4 = wq[h];
            float2 w0 = make_float2(w4.x, w4.y);
            float2 w1 = make_float2(w4.z, w4.w);
            float2 dA0 = padd2f(pA, w0);
            float2 dB0 = padd2f(pB, w0);
            float2 dA1 = padd2f(pA, w1);
            float2 dB1 = padd2f(pB, w1);
            accA[2*h]   = fmaxf(fmaxf(accA[2*h],   fabsf(dA0.x)), fabsf(dA0.y));
            accB[2*h]   = fmaxf(fmaxf(accB[2*h],   fabsf(dB0.x)), fabsf(dB0.y));
            accA[2*h+1] = fmaxf(fmaxf(accA[2*h+1], fabsf(dA1.x)), fabsf(dA1.y));
            accB[2*h+1] = fmaxf(fmaxf(accB[2*h+1], fabsf(dB1.x)), fabsf(dB1.y));
        }
    };

    #pragma unroll
    for (int cp2 = 0; cp2 < 2; cp2++) {        // channel pair within quarter
        const int c0 = cs * 4 + cp2 * 2;
        #pragma unroll
        for (int i = 0; i < 3; i++) {          // kernel row
            // patch: 4x LDS.64; padded cols 2cp..2cp+3 for rows of ch c0, c0+1
            float2 a0 = *reinterpret_cast<const float2*>(&xs[c0    ][r + i][2 * cp]);
            float2 b0 = *reinterpret_cast<const float2*>(&xs[c0    ][r + i][2 * cp + 2]);
            float2 a1 = *reinterpret_cast<const float2*>(&xs[c0 + 1][r + i][2 * cp]);
            float2 b1 = *reinterpret_cast<const float2*>(&xs[c0 + 1][r + i][2 * cp + 2]);

            // P pair ch c0 (taps j0,j1): colA=(a0.x,a0.y) free; colB=(a0.y,b0.x)
            do_pair((cp2 * 2 + 0) * 3 + i, a0, make_float2(a0.y, b0.x));
            // P pair ch c0+1
            do_pair((cp2 * 2 + 1) * 3 + i, a1, make_float2(a1.y, b1.x));
            // R pair (j2 of c0, j2 of c0+1): colA=(b0.x,b1.x), colB=(b0.y,b1.y)
            do_pair(12 + cp2 * 3 + i, make_float2(b0.x, b1.x), make_float2(b0.y, b1.y));
        }
    }

    // ---- reduce the 4 channel-quarters (R12 single-stage)
    if (cs > 0) {
        float* p = &ps[cs - 1][r][cp][0];
        #pragma unroll
        for (int o = 0; o < OCG; o++) { p[o] = accA[o]; p[OCG + o] = accB[o]; }
    }
    __syncthreads();

    if (cs == 0) {
        const int orow = row0 + r;
        float* outp = out + (((size_t)n * OUT_CH + og * OCG) * HDIM + orow) * WDIM + 2 * cp;
        #pragma unroll
        for (int o = 0; o < OCG; o++) {
            float a = fmaxf(fmaxf(accA[o], ps[0][r][cp][o]),
                            fmaxf(ps[1][r][cp][o], ps[2][r][cp][o]));
            float b = fmaxf(fmaxf(accB[o], ps[0][r][cp][OCG + o]),
                            fmaxf(ps[1][r][cp][OCG + o], ps[2][r][cp][OCG + o]));
            const float bi = __ldg(&bias[og * OCG + o]);
            float2 res = make_float2(a + bi, b + bi);
            *reinterpret_cast<float2*>(outp + (size_t)o * HDIM * WDIM) = res;
        }
    }
}

extern "C" void kernel_launch(void* const* d_in, const int* in_sizes, int n_in,
                              void* d_out, int out_size) {
    const float* x      = (const float*)d_in[0];
    const float* weight = (const float*)d_in[1];
    const float* bias   = (const float*)d_in[2];
    float* out          = (float*)d_out;

    dim3 grid(OUT_CH / OCG, HDIM / ROWS, NB);   // (8, 16, 8) = 1024 blocks
    normdist_kernel<<<grid, TPB>>>(x, weight, bias, out);
}

// round 16
// speedup vs baseline: 1.0098x; 1.0098x over previous
#include <cuda_runtime.h>

#define IN_CH 16
#define OUT_CH 64
#define HDIM 32
#define WDIM 32
#define NB 8
#define KHW 9
#define F (IN_CH * KHW)      // 144
#define OCG 8                // out channels per block
#define ROWS 2               // output rows per block
#define NCP 16               // column pairs (2 cols/thread)
#define CSPLIT 4             // input-channel split (lane bits 3:4)
#define CPT 4                // channels per thread
#define TPB 128
#define TW 34                // row width inside a channel plane
#define CSTRIDE 140          // channel plane stride (floats): cs offset 16 banks
#define WCH 296              // per-cs weight chunk stride (floats): 8-bank offset

__global__ __launch_bounds__(TPB, 8) void normdist_kernel(
    const float* __restrict__ x,      // (8,16,32,32)
    const float* __restrict__ weight, // (64,144)
    const float* __restrict__ bias,   // (64)
    float* __restrict__ out)          // (8,64,32,32)
{
    const int og  = blockIdx.x;            // 0..7 out-channel group
    const int rg  = blockIdx.y;            // 0..15 row group
    const int n   = blockIdx.z;            // 0..7 batch
    const int tid = threadIdx.x;
    // lane mapping: b0-2 = cp_low, b3-4 = cs (in-warp!), b5 = cp_high, b6 = r
    const int cs  = (tid >> 3) & 3;
    const int cp  = (tid & 7) | (((tid >> 5) & 1) << 3);   // 0..15
    const int r   = (tid >> 6) & 1;

    const int row0 = rg * ROWS;

    __shared__ float xs[IN_CH * CSTRIDE];                 // 8960 B
    __shared__ __align__(16) float wT[CSPLIT * WCH];      // 4736 B

    // ---- weight loader: wT[csq*WCH + (ci*9+k)*8 + o] = weight[(og*8+o)*144 + f]
    {
        const float* wsrc = weight + og * OCG * F;
        #pragma unroll
        for (int kk = 0; kk < 9; kk++) {       // 9*128 = 1152 exactly
            int idx = tid + kk * TPB;
            int o = idx & 7;
            int f = idx >> 3;                  // 0..143
            int c = f / KHW;
            int k = f - c * KHW;
            int csq = c >> 2, ci = c & 3;
            wT[csq * WCH + (ci * KHW + k) * OCG + o] = wsrc[o * F + f];
        }
    }

    // ---- x tile with halo; shift-only indexing (64 (c,rr) pairs x 2 lanes)
    {
        const float* xn = x + (size_t)n * IN_CH * HDIM * WDIM;
        const int pair = tid >> 1;             // 0..63
        const int l2   = tid & 1;
        const int c    = pair >> 2;            // 0..15
        const int rr   = pair & 3;             // 0..3
        const int gr   = row0 - 1 + rr;
        const bool rok = (gr >= 0) && (gr < HDIM);
        const float* src = xn + (c * HDIM + gr) * WDIM;
        float* dst = &xs[c * CSTRIDE + rr * TW];
        #pragma unroll
        for (int e = 0; e < 17; e++) {         // 17*2 = 34
            int cc = l2 + e * 2;
            int gc = cc - 1;
            float v = 0.0f;
            if (rok && gc >= 0 && gc < WDIM) v = src[gc];
            dst[cc] = v;
        }
    }
    __syncthreads();

    float accA[OCG], accB[OCG];
    #pragma unroll
    for (int o = 0; o < OCG; o++) { accA[o] = 0.0f; accB[o] = 0.0f; }

    const float* xbase = &xs[(cs * CPT) * CSTRIDE + r * TW + 2 * cp];
    const float* wbase = &wT[cs * WCH];

    #pragma unroll
    for (int ci = 0; ci < CPT; ci++) {
        // 3 rows x 4 cols patch segment via aligned LDS.64
        float v[3][4];
        #pragma unroll
        for (int i = 0; i < 3; i++) {
            const float2* row = reinterpret_cast<const float2*>(
                xbase + ci * CSTRIDE + i * TW);
            float2 a = row[0];
            float2 b = row[1];
            v[i][0] = a.x; v[i][1] = a.y; v[i][2] = b.x; v[i][3] = b.y;
        }

        // taps in PAIRS -> FMNMX3: acc = max(max(acc,|d0|),|d1|)
        #pragma unroll
        for (int tp = 0; tp < 4; tp++) {
            const int t0 = 2 * tp, t1 = 2 * tp + 1;
            const int i0 = t0 / 3, j0 = t0 % 3;
            const int i1 = t1 / 3, j1 = t1 % 3;
            const float4* w0 = reinterpret_cast<const float4*>(
                wbase + (ci * KHW + t0) * OCG);
            const float4* w1 = reinterpret_cast<const float4*>(
                wbase + (ci * KHW + t1) * OCG);
            float4 a0 = w0[0], a1 = w0[1];
            float4 b0 = w1[0], b1 = w1[1];
            const float pA0 = v[i0][j0], pB0 = v[i0][j0 + 1];
            const float pA1 = v[i1][j1], pB1 = v[i1][j1 + 1];
            accA[0] = fmaxf(fmaxf(accA[0], fabsf(pA0 - a0.x)), fabsf(pA1 - b0.x));
            accA[1] = fmaxf(fmaxf(accA[1], fabsf(pA0 - a0.y)), fabsf(pA1 - b0.y));
            accA[2] = fmaxf(fmaxf(accA[2], fabsf(pA0 - a0.z)), fabsf(pA1 - b0.z));
            accA[3] = fmaxf(fmaxf(accA[3], fabsf(pA0 - a0.w)), fabsf(pA1 - b0.w));
            accA[4] = fmaxf(fmaxf(accA[4], fabsf(pA0 - a1.x)), fabsf(pA1 - b1.x));
            accA[5] = fmaxf(fmaxf(accA[5], fabsf(pA0 - a1.y)), fabsf(pA1 - b1.y));
            accA[6] = fmaxf(fmaxf(accA[6], fabsf(pA0 - a1.z)), fabsf(pA1 - b1.z));
            accA[7] = fmaxf(fmaxf(accA[7], fabsf(pA0 - a1.w)), fabsf(pA1 - b1.w));
            accB[0] = fmaxf(fmaxf(accB[0], fabsf(pB0 - a0.x)), fabsf(pB1 - b0.x));
            accB[1] = fmaxf(fmaxf(accB[1], fabsf(pB0 - a0.y)), fabsf(pB1 - b0.y));
            accB[2] = fmaxf(fmaxf(accB[2], fabsf(pB0 - a0.z)), fabsf(pB1 - b0.z));
            accB[3] = fmaxf(fmaxf(accB[3], fabsf(pB0 - a0.w)), fabsf(pB1 - b0.w));
            accB[4] = fmaxf(fmaxf(accB[4], fabsf(pB0 - a1.x)), fabsf(pB1 - b1.x));
            accB[5] = fmaxf(fmaxf(accB[5], fabsf(pB0 - a1.y)), fabsf(pB1 - b1.y));
            accB[6] = fmaxf(fmaxf(accB[6], fabsf(pB0 - a1.z)), fabsf(pB1 - b1.z));
            accB[7] = fmaxf(fmaxf(accB[7], fabsf(pB0 - a1.w)), fabsf(pB1 - b1.w));
        }
        // leftover tap 8 (i=2, j=2)
        {
            const float4* w4 = reinterpret_cast<const float4*>(
                wbase + (ci * KHW + 8) * OCG);
            float4 wa = w4[0], wb = w4[1];
            const float pA = v[2][2], pB = v[2][3];
            accA[0] = fmaxf(accA[0], fabsf(pA - wa.x));
            accA[1] = fmaxf(accA[1], fabsf(pA - wa.y));
            accA[2] = fmaxf(accA[2], fabsf(pA - wa.z));
            accA[3] = fmaxf(accA[3], fabsf(pA - wa.w));
            accA[4] = fmaxf(accA[4], fabsf(pA - wb.x));
            accA[5] = fmaxf(accA[5], fabsf(pA - wb.y));
            accA[6] = fmaxf(accA[6], fabsf(pA - wb.z));
            accA[7] = fmaxf(accA[7], fabsf(pA - wb.w));
            accB[0] = fmaxf(accB[0], fabsf(pB - wa.x));
            accB[1] = fmaxf(accB[1], fabsf(pB - wa.y));
            accB[2] = fmaxf(accB[2], fabsf(pB - wa.z));
            accB[3] = fmaxf(accB[3], fabsf(pB - wa.w));
            accB[4] = fmaxf(accB[4], fabsf(pB - wb.x));
            accB[5] = fmaxf(accB[5], fabsf(pB - wb.y));
            accB[6] = fmaxf(accB[6], fabsf(pB - wb.z));
            accB[7] = fmaxf(accB[7], fabsf(pB - wb.w));
        }
    }

    // ---- cross-cs reduction: 2-round butterfly over lane bits 3 (8) and 4 (16)
    #pragma unroll
    for (int o = 0; o < OCG; o++) {
        accA[o] = fmaxf(accA[o], __shfl_xor_sync(0xffffffffu, accA[o], 8));
        accB[o] = fmaxf(accB[o], __shfl_xor_sync(0xffffffffu, accB[o], 8));
    }
    #pragma unroll
    for (int o = 0; o < OCG; o++) {
        accA[o] = fmaxf(accA[o], __shfl_xor_sync(0xffffffffu, accA[o], 16));
        accB[o] = fmaxf(accB[o], __shfl_xor_sync(0xffffffffu, accB[o], 16));
    }

    // ---- epilogue: each thread writes its 2-oc slice (o >> 1 == cs), no barrier
    const int orow = row0 + r;
    float* outp0 = out + (((size_t)n * OUT_CH + og * OCG) * HDIM + orow) * WDIM + 2 * cp;
    #pragma unroll
    for (int o = 0; o < OCG; o++) {
        if ((o >> 1) == cs) {
            const float bi = __ldg(&bias[og * OCG + o]);
            float2 res = make_float2(accA[o] + bi, accB[o] + bi);
            *reinterpret_cast<float2*>(outp0 + (size_t)o * HDIM * WDIM) = res;
        }
    }
}

extern "C" void kernel_launch(void* const* d_in, const int* in_sizes, int n_in,
                              void* d_out, int out_size) {
    const float* x      = (const float*)d_in[0];
    const float* weight = (const float*)d_in[1];
    const float* bias   = (const float*)d_in[2];
    float* out          = (float*)d_out;

    dim3 grid(OUT_CH / OCG, HDIM / ROWS, NB);   // (8, 16, 8) = 1024 blocks
    normdist_kernel<<<grid, TPB>>>(x, weight, bias, out);
}